// round 2
// baseline (speedup 1.0000x reference)
#include <cuda_runtime.h>

#define TB 256
#define BM 128
#define BN 128
#define BK 8

// Scratch (device globals; no allocations allowed).
static __device__ float g_q[16384ull * 768];          // 48 MB
static __device__ float g_k[16384ull * 768];          // 48 MB
static __device__ float g_v[16384ull * 768];          // 48 MB
static __device__ float g_s[8ull * 2048 * 2048];      // 134 MB

// ---------------------------------------------------------------------------
// Shared 8x8 microkernel on a [BK][BM]/[BK][BN] smem slab pair.
// ---------------------------------------------------------------------------
__device__ __forceinline__ void mm_tile(const float (*As)[BM], const float (*Bs)[BN],
                                        int ty, int tx, float acc[8][8]) {
#pragma unroll
    for (int kk = 0; kk < BK; kk++) {
        float4 a0 = *(const float4*)&As[kk][ty * 4];
        float4 a1 = *(const float4*)&As[kk][64 + ty * 4];
        float4 b0 = *(const float4*)&Bs[kk][tx * 4];
        float4 b1 = *(const float4*)&Bs[kk][64 + tx * 4];
        float ar[8] = {a0.x, a0.y, a0.z, a0.w, a1.x, a1.y, a1.z, a1.w};
        float br[8] = {b0.x, b0.y, b0.z, b0.w, b1.x, b1.y, b1.z, b1.w};
#pragma unroll
        for (int i = 0; i < 8; i++)
#pragma unroll
            for (int j = 0; j < 8; j++)
                acc[i][j] = fmaf(ar[i], br[j], acc[i][j]);
    }
}

// ---------------------------------------------------------------------------
// GEMM 1: qkv = X[16384,768] @ W[768,2304] + bias, scattered into g_q/g_k/g_v
// Double-buffered smem pipeline.
// ---------------------------------------------------------------------------
__global__ void __launch_bounds__(TB) qkv_gemm(const float* __restrict__ X,
                                               const float* __restrict__ W,
                                               const float* __restrict__ bias) {
    const int K = 768, N = 2304;
    __shared__ float As[2][BK][BM];
    __shared__ float Bs[2][BK][BN];
    const int m0 = blockIdx.y * BM;
    const int n0 = blockIdx.x * BN;
    const int tid = threadIdx.x;
    const int tx = tid & 15, ty = tid >> 4;
    const int arow = tid >> 1, acol = (tid & 1) * 4;
    const int brow = tid >> 5, bcol = (tid & 31) * 4;

    float acc[8][8] = {};
    const float* Aptr = X + (size_t)(m0 + arow) * K + acol;
    const float* Bptr = W + (size_t)brow * N + n0 + bcol;

    // Prologue: slab 0 into buffer 0
    {
        float4 a = *(const float4*)(Aptr);
        float4 b = *(const float4*)(Bptr);
        As[0][acol + 0][arow] = a.x;
        As[0][acol + 1][arow] = a.y;
        As[0][acol + 2][arow] = a.z;
        As[0][acol + 3][arow] = a.w;
        *(float4*)&Bs[0][brow][bcol] = b;
    }
    __syncthreads();

    const int nt = K / BK;
    for (int t = 0; t < nt; t++) {
        const int cur = t & 1;
        float4 a, b;
        const bool more = (t + 1 < nt);
        if (more) {
            int k0 = (t + 1) * BK;
            a = *(const float4*)(Aptr + k0);
            b = *(const float4*)(Bptr + (size_t)k0 * N);
        }
        mm_tile(As[cur], Bs[cur], ty, tx, acc);
        if (more) {
            const int nxt = cur ^ 1;
            As[nxt][acol + 0][arow] = a.x;
            As[nxt][acol + 1][arow] = a.y;
            As[nxt][acol + 2][arow] = a.z;
            As[nxt][acol + 3][arow] = a.w;
            *(float4*)&Bs[nxt][brow][bcol] = b;
        }
        __syncthreads();
    }

#pragma unroll
    for (int i = 0; i < 8; i++) {
        int rm = (i < 4) ? (ty * 4 + i) : (64 + ty * 4 + (i - 4));
        size_t grow = (size_t)(m0 + rm);
#pragma unroll
        for (int jb = 0; jb < 2; jb++) {
            int cn = (jb == 0) ? (tx * 4) : (64 + tx * 4);
            int gc = n0 + cn;
            float4 r;
            r.x = acc[i][jb * 4 + 0] + bias[gc + 0];
            r.y = acc[i][jb * 4 + 1] + bias[gc + 1];
            r.z = acc[i][jb * 4 + 2] + bias[gc + 2];
            r.w = acc[i][jb * 4 + 3] + bias[gc + 3];
            float* dst;
            if (gc < 768)       dst = g_q + grow * 768 + gc;
            else if (gc < 1536) dst = g_k + grow * 768 + (gc - 768);
            else                dst = g_v + grow * 768 + (gc - 1536);
            *(float4*)dst = r;
        }
    }
}

// ---------------------------------------------------------------------------
// GEMM 2 (NT): S = Q @ K^T * scale, per batch. M=N=2048, K=768
// ---------------------------------------------------------------------------
__global__ void __launch_bounds__(TB) scores_gemm() {
    const int K = 768;
    const float SCALE = 0.03608439182435161f;  // 1/sqrt(768)
    const int z = blockIdx.z;
    const float* Q  = g_q + (size_t)z * 2048 * 768;
    const float* Km = g_k + (size_t)z * 2048 * 768;
    float* S = g_s + (size_t)z * 2048 * 2048;

    __shared__ float As[2][BK][BM];
    __shared__ float Bs[2][BK][BN];
    const int m0 = blockIdx.y * BM;
    const int n0 = blockIdx.x * BN;
    const int tid = threadIdx.x;
    const int tx = tid & 15, ty = tid >> 4;
    const int arow = tid >> 1, acol = (tid & 1) * 4;

    float acc[8][8] = {};
    const float* Aptr = Q + (size_t)(m0 + arow) * K + acol;
    const float* Bptr = Km + (size_t)(n0 + arow) * K + acol;

    {
        float4 a = *(const float4*)(Aptr);
        float4 b = *(const float4*)(Bptr);
        As[0][acol + 0][arow] = a.x;
        As[0][acol + 1][arow] = a.y;
        As[0][acol + 2][arow] = a.z;
        As[0][acol + 3][arow] = a.w;
        Bs[0][acol + 0][arow] = b.x;
        Bs[0][acol + 1][arow] = b.y;
        Bs[0][acol + 2][arow] = b.z;
        Bs[0][acol + 3][arow] = b.w;
    }
    __syncthreads();

    const int nt = K / BK;
    for (int t = 0; t < nt; t++) {
        const int cur = t & 1;
        float4 a, b;
        const bool more = (t + 1 < nt);
        if (more) {
            int k0 = (t + 1) * BK;
            a = *(const float4*)(Aptr + k0);
            b = *(const float4*)(Bptr + k0);
        }
        mm_tile(As[cur], Bs[cur], ty, tx, acc);
        if (more) {
            const int nxt = cur ^ 1;
            As[nxt][acol + 0][arow] = a.x;
            As[nxt][acol + 1][arow] = a.y;
            As[nxt][acol + 2][arow] = a.z;
            As[nxt][acol + 3][arow] = a.w;
            Bs[nxt][acol + 0][arow] = b.x;
            Bs[nxt][acol + 1][arow] = b.y;
            Bs[nxt][acol + 2][arow] = b.z;
            Bs[nxt][acol + 3][arow] = b.w;
        }
        __syncthreads();
    }

#pragma unroll
    for (int i = 0; i < 8; i++) {
        int rm = (i < 4) ? (ty * 4 + i) : (64 + ty * 4 + (i - 4));
        size_t grow = (size_t)(m0 + rm);
#pragma unroll
        for (int jb = 0; jb < 2; jb++) {
            int cn = (jb == 0) ? (tx * 4) : (64 + tx * 4);
            int gc = n0 + cn;
            float4 r;
            r.x = acc[i][jb * 4 + 0] * SCALE;
            r.y = acc[i][jb * 4 + 1] * SCALE;
            r.z = acc[i][jb * 4 + 2] * SCALE;
            r.w = acc[i][jb * 4 + 3] * SCALE;
            *(float4*)(S + grow * 2048 + gc) = r;
        }
    }
}

// ---------------------------------------------------------------------------
// Row softmax over g_s: 16384 rows x 2048 cols. One block per row.
// ---------------------------------------------------------------------------
__global__ void __launch_bounds__(256) softmax_rows() {
    __shared__ float red[8];
    __shared__ float bcast;
    float* p = g_s + (size_t)blockIdx.x * 2048;
    const int t = threadIdx.x;
    const int lane = t & 31, wid = t >> 5;

    float v[8];
    float4 u0 = *(const float4*)(p + t * 8);
    float4 u1 = *(const float4*)(p + t * 8 + 4);
    v[0] = u0.x; v[1] = u0.y; v[2] = u0.z; v[3] = u0.w;
    v[4] = u1.x; v[5] = u1.y; v[6] = u1.z; v[7] = u1.w;

    float m = v[0];
#pragma unroll
    for (int i = 1; i < 8; i++) m = fmaxf(m, v[i]);
#pragma unroll
    for (int o = 16; o > 0; o >>= 1) m = fmaxf(m, __shfl_xor_sync(0xFFFFFFFFu, m, o));
    if (lane == 0) red[wid] = m;
    __syncthreads();
    if (t == 0) {
        float mm = red[0];
#pragma unroll
        for (int i = 1; i < 8; i++) mm = fmaxf(mm, red[i]);
        bcast = mm;
    }
    __syncthreads();
    const float rowmax = bcast;
    __syncthreads();

    float s = 0.f;
#pragma unroll
    for (int i = 0; i < 8; i++) {
        v[i] = __expf(v[i] - rowmax);
        s += v[i];
    }
#pragma unroll
    for (int o = 16; o > 0; o >>= 1) s += __shfl_xor_sync(0xFFFFFFFFu, s, o);
    if (lane == 0) red[wid] = s;
    __syncthreads();
    if (t == 0) {
        float ss = red[0];
#pragma unroll
        for (int i = 1; i < 8; i++) ss += red[i];
        bcast = ss;
    }
    __syncthreads();
    const float inv = 1.0f / bcast;

    float4 w0, w1;
    w0.x = v[0] * inv; w0.y = v[1] * inv; w0.z = v[2] * inv; w0.w = v[3] * inv;
    w1.x = v[4] * inv; w1.y = v[5] * inv; w1.z = v[6] * inv; w1.w = v[7] * inv;
    *(float4*)(p + t * 8) = w0;
    *(float4*)(p + t * 8 + 4) = w1;
}

// ---------------------------------------------------------------------------
// GEMM 3 (NN): O = P @ V, per batch. M=2048, N=768, K=2048
// ---------------------------------------------------------------------------
__global__ void __launch_bounds__(TB) out_gemm(float* __restrict__ O) {
    const int K = 2048, N = 768;
    const int z = blockIdx.z;
    const float* P = g_s + (size_t)z * 2048 * 2048;
    const float* V = g_v + (size_t)z * 2048 * 768;
    float* Ob = O + (size_t)z * 2048 * 768;

    __shared__ float As[2][BK][BM];
    __shared__ float Bs[2][BK][BN];
    const int m0 = blockIdx.y * BM;
    const int n0 = blockIdx.x * BN;
    const int tid = threadIdx.x;
    const int tx = tid & 15, ty = tid >> 4;
    const int arow = tid >> 1, acol = (tid & 1) * 4;
    const int brow = tid >> 5, bcol = (tid & 31) * 4;

    float acc[8][8] = {};
    const float* Aptr = P + (size_t)(m0 + arow) * K + acol;
    const float* Bptr = V + (size_t)brow * N + n0 + bcol;

    {
        float4 a = *(const float4*)(Aptr);
        float4 b = *(const float4*)(Bptr);
        As[0][acol + 0][arow] = a.x;
        As[0][acol + 1][arow] = a.y;
        As[0][acol + 2][arow] = a.z;
        As[0][acol + 3][arow] = a.w;
        *(float4*)&Bs[0][brow][bcol] = b;
    }
    __syncthreads();

    const int nt = K / BK;
    for (int t = 0; t < nt; t++) {
        const int cur = t & 1;
        float4 a, b;
        const bool more = (t + 1 < nt);
        if (more) {
            int k0 = (t + 1) * BK;
            a = *(const float4*)(Aptr + k0);
            b = *(const float4*)(Bptr + (size_t)k0 * N);
        }
        mm_tile(As[cur], Bs[cur], ty, tx, acc);
        if (more) {
            const int nxt = cur ^ 1;
            As[nxt][acol + 0][arow] = a.x;
            As[nxt][acol + 1][arow] = a.y;
            As[nxt][acol + 2][arow] = a.z;
            As[nxt][acol + 3][arow] = a.w;
            *(float4*)&Bs[nxt][brow][bcol] = b;
        }
        __syncthreads();
    }

#pragma unroll
    for (int i = 0; i < 8; i++) {
        int rm = (i < 4) ? (ty * 4 + i) : (64 + ty * 4 + (i - 4));
        size_t grow = (size_t)(m0 + rm);
#pragma unroll
        for (int jb = 0; jb < 2; jb++) {
            int cn = (jb == 0) ? (tx * 4) : (64 + tx * 4);
            int gc = n0 + cn;
            float4 r;
            r.x = acc[i][jb * 4 + 0];
            r.y = acc[i][jb * 4 + 1];
            r.z = acc[i][jb * 4 + 2];
            r.w = acc[i][jb * 4 + 3];
            *(float4*)(Ob + grow * N + gc) = r;
        }
    }
}

// ---------------------------------------------------------------------------
extern "C" void kernel_launch(void* const* d_in, const int* in_sizes, int n_in,
                              void* d_out, int out_size) {
    const float* x    = (const float*)d_in[0];  // [8,2048,768]
    const float* Wq   = (const float*)d_in[1];  // [768,2304]
    const float* bq   = (const float*)d_in[2];  // [2304]
    float* out = (float*)d_out;                  // [8,2048,768]

    qkv_gemm<<<dim3(2304 / BN, 16384 / BM), TB>>>(x, Wq, bq);
    scores_gemm<<<dim3(2048 / BN, 2048 / BM, 8), TB>>>();
    softmax_rows<<<16384, 256>>>();
    out_gemm<<<dim3(768 / BN, 2048 / BM, 8), TB>>>(out);
}

// round 4
// speedup vs baseline: 1.9609x; 1.9609x over previous
#include <cuda_runtime.h>
#include <cuda_bf16.h>
#include <cstdint>

// ---------------- problem dims ----------------
#define BATCH 8
#define SEQ   2048
#define DIN   768
#define DOUT  768
#define MTOT  16384
#define NQKV  2304

// ---------------- tiling ----------------
#define BM 128
#define BN 128
#define KC 32                    // bf16 elems per K chunk
#define LDT 40                   // smem row stride in bf16 (80 B, 16B-aligned, pad vs 32)
#define TILE_BYTES (BM * LDT * 2)        // 10240
#define STAGE_BYTES (4 * TILE_BYTES)     // 40960 (Ahi,Alo,Bhi,Blo)
#define NSTAGE 2
#define SMEM_TOTAL (NSTAGE * STAGE_BYTES) // 81920

// ---------------- scratch ----------------
static __device__ __nv_bfloat16 g_xhi[(size_t)MTOT * DIN];
static __device__ __nv_bfloat16 g_xlo[(size_t)MTOT * DIN];
static __device__ __nv_bfloat16 g_wthi[(size_t)NQKV * DIN];
static __device__ __nv_bfloat16 g_wtlo[(size_t)NQKV * DIN];
static __device__ __nv_bfloat16 g_qhi[(size_t)MTOT * DOUT];
static __device__ __nv_bfloat16 g_qlo[(size_t)MTOT * DOUT];
static __device__ __nv_bfloat16 g_khi[(size_t)MTOT * DOUT];
static __device__ __nv_bfloat16 g_klo[(size_t)MTOT * DOUT];
static __device__ __nv_bfloat16 g_vthi[(size_t)BATCH * DOUT * SEQ];  // [b][feat][tok]
static __device__ __nv_bfloat16 g_vtlo[(size_t)BATCH * DOUT * SEQ];
static __device__ float         g_s[(size_t)BATCH * SEQ * SEQ];
static __device__ __nv_bfloat16 g_phi[(size_t)BATCH * SEQ * SEQ];
static __device__ __nv_bfloat16 g_plo[(size_t)BATCH * SEQ * SEQ];

// ---------------- helpers ----------------
__device__ __forceinline__ uint32_t smem_u32(const void* p) {
    uint32_t a;
    asm("{ .reg .u64 t; cvta.to.shared.u64 t, %1; cvt.u32.u64 %0, t; }" : "=r"(a) : "l"(p));
    return a;
}
__device__ __forceinline__ void cp16(uint32_t dst, const void* src) {
    asm volatile("cp.async.cg.shared.global [%0], [%1], 16;" :: "r"(dst), "l"(src));
}
#define CP_COMMIT() asm volatile("cp.async.commit_group;" ::: "memory")
#define CP_WAIT0()  asm volatile("cp.async.wait_group 0;" ::: "memory")

#define LDSM4(r0, r1, r2, r3, addr) \
    asm volatile("ldmatrix.sync.aligned.m8n8.x4.shared.b16 {%0,%1,%2,%3}, [%4];" \
        : "=r"(r0), "=r"(r1), "=r"(r2), "=r"(r3) : "r"(addr))

#define MMA_BF16(c, a, b) \
    asm volatile("mma.sync.aligned.m16n8k16.row.col.f32.bf16.bf16.f32 " \
        "{%0,%1,%2,%3}, {%4,%5,%6,%7}, {%8,%9}, {%0,%1,%2,%3};" \
        : "+f"((c)[0]), "+f"((c)[1]), "+f"((c)[2]), "+f"((c)[3]) \
        : "r"((a)[0]), "r"((a)[1]), "r"((a)[2]), "r"((a)[3]), "r"((b)[0]), "r"((b)[1]))

__device__ __forceinline__ void split2(float v, __nv_bfloat16& h, __nv_bfloat16& l) {
    h = __float2bfloat16_rn(v);
    l = __float2bfloat16_rn(v - __bfloat162float(h));
}

// Load one 128x32 bf16 tile into smem (row stride LDT), 2 x 16B per thread.
__device__ __forceinline__ void load_tile(uint32_t sdst, const __nv_bfloat16* g,
                                          int ld, int tid) {
#pragma unroll
    for (int p = 0; p < 2; p++) {
        int c = tid + p * 256;
        int row = c >> 2, seg = c & 3;
        cp16(sdst + row * (LDT * 2) + seg * 16, g + (size_t)row * ld + seg * 8);
    }
}
__device__ __forceinline__ void load_stage(uint32_t sb,
                                           const __nv_bfloat16* Ahi, const __nv_bfloat16* Alo,
                                           const __nv_bfloat16* Bhi, const __nv_bfloat16* Blo,
                                           int lda, int ldb, int k0, int tid) {
    load_tile(sb + 0 * TILE_BYTES, Ahi + k0, lda, tid);
    load_tile(sb + 1 * TILE_BYTES, Alo + k0, lda, tid);
    load_tile(sb + 2 * TILE_BYTES, Bhi + k0, ldb, tid);
    load_tile(sb + 3 * TILE_BYTES, Blo + k0, ldb, tid);
    CP_COMMIT();
}

// One 128x128x32 chunk of 3-product bf16-split MMA for this warp (32x64 tile).
__device__ __forceinline__ void compute_chunk(uint32_t sb, uint32_t aOff, uint32_t bOff,
                                              float acc[2][8][4]) {
    const uint32_t sAhi = sb, sAlo = sb + TILE_BYTES;
    const uint32_t sBhi = sb + 2 * TILE_BYTES, sBlo = sb + 3 * TILE_BYTES;
#pragma unroll
    for (int kk = 0; kk < 2; kk++) {
        uint32_t ah[8], al[8];
        LDSM4(ah[0], ah[1], ah[2], ah[3], sAhi + aOff + kk * 32);
        LDSM4(ah[4], ah[5], ah[6], ah[7], sAhi + aOff + kk * 32 + 16 * LDT * 2);
        LDSM4(al[0], al[1], al[2], al[3], sAlo + aOff + kk * 32);
        LDSM4(al[4], al[5], al[6], al[7], sAlo + aOff + kk * 32 + 16 * LDT * 2);
#pragma unroll
        for (int g = 0; g < 4; g++) {
            uint32_t bh[4], bl[4];
            LDSM4(bh[0], bh[1], bh[2], bh[3], sBhi + bOff + kk * 32 + g * 16 * LDT * 2);
            LDSM4(bl[0], bl[1], bl[2], bl[3], sBlo + bOff + kk * 32 + g * 16 * LDT * 2);
#pragma unroll
            for (int f = 0; f < 2; f++) {
#pragma unroll
                for (int mi = 0; mi < 2; mi++) {
                    MMA_BF16(acc[mi][g * 2 + f], ah + mi * 4, bh + f * 2);
                    MMA_BF16(acc[mi][g * 2 + f], ah + mi * 4, bl + f * 2);
                    MMA_BF16(acc[mi][g * 2 + f], al + mi * 4, bh + f * 2);
                }
            }
        }
    }
}

// Full mainloop: acc = A[128 rows, K] . B[128 rows, K]^T (hi/lo split, NT).
__device__ __forceinline__ void gemm_mainloop(const __nv_bfloat16* Ahi, const __nv_bfloat16* Alo,
                                              const __nv_bfloat16* Bhi, const __nv_bfloat16* Blo,
                                              int lda, int ldb, int nk,
                                              uint32_t su, float acc[2][8][4]) {
    const int tid = threadIdx.x;
    const int lane = tid & 31, warp = tid >> 5;
    const int wm = warp & 3, wn = warp >> 2;
    const uint32_t aOff = ((wm * 32 + (lane & 15)) * LDT + ((lane >> 4) & 1) * 8) * 2;
    const uint32_t bOff = ((wn * 64 + (lane & 7) + ((lane >> 4) & 1) * 8) * LDT
                           + ((lane >> 3) & 1) * 8) * 2;

    load_stage(su, Ahi, Alo, Bhi, Blo, lda, ldb, 0, tid);
    for (int t = 0; t < nk; t++) {
        CP_WAIT0();
        __syncthreads();
        if (t + 1 < nk)
            load_stage(su + ((t + 1) & 1) * STAGE_BYTES, Ahi, Alo, Bhi, Blo,
                       lda, ldb, (t + 1) * KC, tid);
        compute_chunk(su + (t & 1) * STAGE_BYTES, aOff, bOff, acc);
    }
}

// ---------------- conversion kernels ----------------
__global__ void __launch_bounds__(256) conv_x(const float* __restrict__ x) {
    size_t i = ((size_t)blockIdx.x * 256 + threadIdx.x) * 4;
    float4 v = *(const float4*)(x + i);
    __nv_bfloat16 h[4], l[4];
    split2(v.x, h[0], l[0]); split2(v.y, h[1], l[1]);
    split2(v.z, h[2], l[2]); split2(v.w, h[3], l[3]);
    ushort4 ph = {__bfloat16_as_ushort(h[0]), __bfloat16_as_ushort(h[1]),
                  __bfloat16_as_ushort(h[2]), __bfloat16_as_ushort(h[3])};
    ushort4 pl = {__bfloat16_as_ushort(l[0]), __bfloat16_as_ushort(l[1]),
                  __bfloat16_as_ushort(l[2]), __bfloat16_as_ushort(l[3])};
    *(ushort4*)(g_xhi + i) = ph;
    *(ushort4*)(g_xlo + i) = pl;
}

__global__ void __launch_bounds__(768) conv_w(const float* __restrict__ W) {
    int n = blockIdx.x, k = threadIdx.x;
    float v = W[(size_t)k * NQKV + n];
    __nv_bfloat16 h, l; split2(v, h, l);
    g_wthi[(size_t)n * DIN + k] = h;
    g_wtlo[(size_t)n * DIN + k] = l;
}

// ---------------- GEMM 1: QKV projection ----------------
__global__ void __launch_bounds__(256) qkv_mm(const float* __restrict__ bias) {
    extern __shared__ char smem[];
    uint32_t su = smem_u32(smem);
    const int m0 = blockIdx.y * BM, n0 = blockIdx.x * BN;
    const int lane = threadIdx.x & 31, warp = threadIdx.x >> 5;
    const int wm = warp & 3, wn = warp >> 2;

    float acc[2][8][4] = {};
    gemm_mainloop(g_xhi + (size_t)m0 * DIN, g_xlo + (size_t)m0 * DIN,
                  g_wthi + (size_t)n0 * DIN, g_wtlo + (size_t)n0 * DIN,
                  DIN, DIN, DIN / KC, su, acc);

    const int region = blockIdx.x / 6;  // 0=Q 1=K 2=V
#pragma unroll
    for (int mi = 0; mi < 2; mi++) {
#pragma unroll
        for (int j = 0; j < 8; j++) {
            int r0 = m0 + wm * 32 + mi * 16 + (lane >> 2);
            int col = n0 + wn * 64 + j * 8 + (lane & 3) * 2;
            float b0 = bias[col], b1 = bias[col + 1];
            float v00 = acc[mi][j][0] + b0, v01 = acc[mi][j][1] + b1;
            float v10 = acc[mi][j][2] + b0, v11 = acc[mi][j][3] + b1;
            if (region < 2) {
                int cl = col - region * DOUT;
                __nv_bfloat16* dh = region == 0 ? g_qhi : g_khi;
                __nv_bfloat16* dl = region == 0 ? g_qlo : g_klo;
                __nv_bfloat16 h0, l0, h1, l1;
                split2(v00, h0, l0); split2(v01, h1, l1);
                *(ushort2*)(dh + (size_t)r0 * DOUT + cl) =
                    {__bfloat16_as_ushort(h0), __bfloat16_as_ushort(h1)};
                *(ushort2*)(dl + (size_t)r0 * DOUT + cl) =
                    {__bfloat16_as_ushort(l0), __bfloat16_as_ushort(l1)};
                split2(v10, h0, l0); split2(v11, h1, l1);
                *(ushort2*)(dh + (size_t)(r0 + 8) * DOUT + cl) =
                    {__bfloat16_as_ushort(h0), __bfloat16_as_ushort(h1)};
                *(ushort2*)(dl + (size_t)(r0 + 8) * DOUT + cl) =
                    {__bfloat16_as_ushort(l0), __bfloat16_as_ushort(l1)};
            } else {
                int feat = col - 2 * DOUT;
#pragma unroll
                for (int rr = 0; rr < 2; rr++) {
                    int mg = r0 + rr * 8;
                    int b = mg >> 11, tok = mg & 2047;
                    size_t base = (size_t)b * DOUT * SEQ + tok;
                    float va = rr ? v10 : v00, vb = rr ? v11 : v01;
                    __nv_bfloat16 h, l;
                    split2(va, h, l);
                    g_vthi[base + (size_t)feat * SEQ] = h;
                    g_vtlo[base + (size_t)feat * SEQ] = l;
                    split2(vb, h, l);
                    g_vthi[base + (size_t)(feat + 1) * SEQ] = h;
                    g_vtlo[base + (size_t)(feat + 1) * SEQ] = l;
                }
            }
        }
    }
}

// ---------------- GEMM 2: scores = Q.K^T * scale ----------------
__global__ void __launch_bounds__(256) scores_mm() {
    extern __shared__ char smem[];
    uint32_t su = smem_u32(smem);
    const int m0 = blockIdx.y * BM, n0 = blockIdx.x * BN, z = blockIdx.z;
    const int lane = threadIdx.x & 31, warp = threadIdx.x >> 5;
    const int wm = warp & 3, wn = warp >> 2;
    const size_t off = (size_t)z * SEQ * DOUT;
    const float SCALE = 0.03608439182435161f;

    float acc[2][8][4] = {};
    gemm_mainloop(g_qhi + off + (size_t)m0 * DOUT, g_qlo + off + (size_t)m0 * DOUT,
                  g_khi + off + (size_t)n0 * DOUT, g_klo + off + (size_t)n0 * DOUT,
                  DOUT, DOUT, DOUT / KC, su, acc);

    float* S = g_s + (size_t)z * SEQ * SEQ;
#pragma unroll
    for (int mi = 0; mi < 2; mi++) {
#pragma unroll
        for (int j = 0; j < 8; j++) {
            int r0 = m0 + wm * 32 + mi * 16 + (lane >> 2);
            int col = n0 + wn * 64 + j * 8 + (lane & 3) * 2;
            *(float2*)(S + (size_t)r0 * SEQ + col) =
                {acc[mi][j][0] * SCALE, acc[mi][j][1] * SCALE};
            *(float2*)(S + (size_t)(r0 + 8) * SEQ + col) =
                {acc[mi][j][2] * SCALE, acc[mi][j][3] * SCALE};
        }
    }
}

// ---------------- softmax + bf16 split of P ----------------
__global__ void __launch_bounds__(256) softmax_rows() {
    __shared__ float red[8];
    __shared__ float bcast;
    const size_t roff = (size_t)blockIdx.x * SEQ;
    const float* p = g_s + roff;
    const int t = threadIdx.x, lane = t & 31, wid = t >> 5;

    float v[8];
    float4 u0 = *(const float4*)(p + t * 8);
    float4 u1 = *(const float4*)(p + t * 8 + 4);
    v[0] = u0.x; v[1] = u0.y; v[2] = u0.z; v[3] = u0.w;
    v[4] = u1.x; v[5] = u1.y; v[6] = u1.z; v[7] = u1.w;

    float m = v[0];
#pragma unroll
    for (int i = 1; i < 8; i++) m = fmaxf(m, v[i]);
#pragma unroll
    for (int o = 16; o > 0; o >>= 1) m = fmaxf(m, __shfl_xor_sync(0xFFFFFFFFu, m, o));
    if (lane == 0) red[wid] = m;
    __syncthreads();
    if (t == 0) {
        float mm = red[0];
#pragma unroll
        for (int i = 1; i < 8; i++) mm = fmaxf(mm, red[i]);
        bcast = mm;
    }
    __syncthreads();
    const float rowmax = bcast;
    __syncthreads();

    float s = 0.f;
#pragma unroll
    for (int i = 0; i < 8; i++) { v[i] = __expf(v[i] - rowmax); s += v[i]; }
#pragma unroll
    for (int o = 16; o > 0; o >>= 1) s += __shfl_xor_sync(0xFFFFFFFFu, s, o);
    if (lane == 0) red[wid] = s;
    __syncthreads();
    if (t == 0) {
        float ss = red[0];
#pragma unroll
        for (int i = 1; i < 8; i++) ss += red[i];
        bcast = ss;
    }
    __syncthreads();
    const float inv = 1.0f / bcast;

    __nv_bfloat16 h[8], l[8];
#pragma unroll
    for (int i = 0; i < 8; i++) split2(v[i] * inv, h[i], l[i]);
#pragma unroll
    for (int g = 0; g < 2; g++) {
        ushort4 ph = {__bfloat16_as_ushort(h[g * 4 + 0]), __bfloat16_as_ushort(h[g * 4 + 1]),
                      __bfloat16_as_ushort(h[g * 4 + 2]), __bfloat16_as_ushort(h[g * 4 + 3])};
        ushort4 pl = {__bfloat16_as_ushort(l[g * 4 + 0]), __bfloat16_as_ushort(l[g * 4 + 1]),
                      __bfloat16_as_ushort(l[g * 4 + 2]), __bfloat16_as_ushort(l[g * 4 + 3])};
        *(ushort4*)(g_phi + roff + t * 8 + g * 4) = ph;
        *(ushort4*)(g_plo + roff + t * 8 + g * 4) = pl;
    }
}

// ---------------- GEMM 3: context = P @ V ----------------
__global__ void __launch_bounds__(256) out_mm(float* __restrict__ out) {
    extern __shared__ char smem[];
    uint32_t su = smem_u32(smem);
    const int m0 = blockIdx.y * BM, n0 = blockIdx.x * BN, z = blockIdx.z;
    const int lane = threadIdx.x & 31, warp = threadIdx.x >> 5;
    const int wm = warp & 3, wn = warp >> 2;
    const size_t p_off = (size_t)z * SEQ * SEQ;
    const size_t v_off = (size_t)z * DOUT * SEQ;

    float acc[2][8][4] = {};
    gemm_mainloop(g_phi + p_off + (size_t)m0 * SEQ, g_plo + p_off + (size_t)m0 * SEQ,
                  g_vthi + v_off + (size_t)n0 * SEQ, g_vtlo + v_off + (size_t)n0 * SEQ,
                  SEQ, SEQ, SEQ / KC, su, acc);

    float* O = out + (size_t)z * SEQ * DOUT;
#pragma unroll
    for (int mi = 0; mi < 2; mi++) {
#pragma unroll
        for (int j = 0; j < 8; j++) {
            int r0 = m0 + wm * 32 + mi * 16 + (lane >> 2);
            int col = n0 + wn * 64 + j * 8 + (lane & 3) * 2;
            *(float2*)(O + (size_t)r0 * DOUT + col) = {acc[mi][j][0], acc[mi][j][1]};
            *(float2*)(O + (size_t)(r0 + 8) * DOUT + col) = {acc[mi][j][2], acc[mi][j][3]};
        }
    }
}

// ---------------------------------------------------------------------------
extern "C" void kernel_launch(void* const* d_in, const int* in_sizes, int n_in,
                              void* d_out, int out_size) {
    const float* x  = (const float*)d_in[0];
    const float* W  = (const float*)d_in[1];
    const float* bq = (const float*)d_in[2];
    float* out = (float*)d_out;

    cudaFuncSetAttribute(qkv_mm,    cudaFuncAttributeMaxDynamicSharedMemorySize, SMEM_TOTAL);
    cudaFuncSetAttribute(scores_mm, cudaFuncAttributeMaxDynamicSharedMemorySize, SMEM_TOTAL);
    cudaFuncSetAttribute(out_mm,    cudaFuncAttributeMaxDynamicSharedMemorySize, SMEM_TOTAL);

    conv_x<<<(MTOT * DIN) / (256 * 4), 256>>>(x);
    conv_w<<<NQKV, 768>>>(W);
    qkv_mm<<<dim3(NQKV / BN, MTOT / BM), 256, SMEM_TOTAL>>>(bq);
    scores_mm<<<dim3(SEQ / BN, SEQ / BM, BATCH), 256, SMEM_TOTAL>>>();
    softmax_rows<<<BATCH * SEQ, 256>>>();
    out_mm<<<dim3(DOUT / BN, SEQ / BM, BATCH), 256, SMEM_TOTAL>>>(out);
}